// round 7
// baseline (speedup 1.0000x reference)
#include <cuda_runtime.h>
#include <cuda_bf16.h>
#include <cstdint>

#define BATCH   4
#define SEQ     512
#define DMODEL  512
#define MROWS   (BATCH * SEQ)       // 2048
#define NHEADS  64                  // "head" axis = d_k in this module
#define HDIM    8                   // per-head feature dim

// ---------------------------------------------------------------------------
// Scratch (no cudaMalloc allowed)
// ---------------------------------------------------------------------------
__device__ float g_qn[MROWS * DMODEL];
__device__ float g_Qp[MROWS * DMODEL];
__device__ float g_Kp[MROWS * DMODEL];
__device__ float g_Vp[MROWS * DMODEL];
__device__ float g_O [MROWS * DMODEL];

// ---------------------------------------------------------------------------
// LayerNorm over last dim (512), one block per row
// ---------------------------------------------------------------------------
__global__ __launch_bounds__(256) void ln_kernel(
    const float* __restrict__ x, const float* __restrict__ gamma,
    const float* __restrict__ beta, float* __restrict__ out)
{
    int row = blockIdx.x;
    const float* xr = x + (size_t)row * DMODEL;
    int tid = threadIdx.x;
    float a0 = xr[tid];
    float a1 = xr[tid + 256];

    __shared__ float red[8];
    __shared__ float red2[8];
    int warp = tid >> 5, lane = tid & 31;

    float s = a0 + a1;
    #pragma unroll
    for (int o = 16; o; o >>= 1) s += __shfl_xor_sync(0xffffffffu, s, o);
    if (lane == 0) red[warp] = s;
    __syncthreads();
    float mean = (red[0] + red[1] + red[2] + red[3] +
                  red[4] + red[5] + red[6] + red[7]) * (1.0f / 512.0f);

    float d0 = a0 - mean, d1 = a1 - mean;
    float vs = d0 * d0 + d1 * d1;
    #pragma unroll
    for (int o = 16; o; o >>= 1) vs += __shfl_xor_sync(0xffffffffu, vs, o);
    if (lane == 0) red2[warp] = vs;
    __syncthreads();
    float var = (red2[0] + red2[1] + red2[2] + red2[3] +
                 red2[4] + red2[5] + red2[6] + red2[7]) * (1.0f / 512.0f);
    float inv = rsqrtf(var + 1e-6f);

    float* orow = out + (size_t)row * DMODEL;
    orow[tid]       = d0 * inv * gamma[tid]       + beta[tid];
    orow[tid + 256] = d1 * inv * gamma[tid + 256] + beta[tid + 256];
}

// ---------------------------------------------------------------------------
// Tensor-core GEMM (bf16 3-pass split, fp32 accumulate) — unchanged winner.
// ---------------------------------------------------------------------------
#define MMA_BF16(d, a, b)                                                    \
    asm volatile(                                                            \
        "mma.sync.aligned.m16n8k16.row.col.f32.bf16.bf16.f32 "              \
        "{%0,%1,%2,%3}, {%4,%5,%6,%7}, {%8,%9}, {%0,%1,%2,%3};"             \
        : "+f"(d[0]), "+f"(d[1]), "+f"(d[2]), "+f"(d[3])                     \
        : "r"(a[0]), "r"(a[1]), "r"(a[2]), "r"(a[3]), "r"(b[0]), "r"(b[1]))

__global__ __launch_bounds__(256) void gemm_bf16x3(
    const float* __restrict__ A0, const float* __restrict__ A1,
    const float* __restrict__ A2,
    const float* __restrict__ W0, const float* __restrict__ W1,
    const float* __restrict__ W2,
    float* __restrict__ C0, float* __restrict__ C1, float* __restrict__ C2,
    const float* __restrict__ bias, const float* __restrict__ resid)
{
    const int K = DMODEL;
    __shared__ __nv_bfloat16 As[2][2][128][24];
    __shared__ __nv_bfloat16 Bs[2][2][64][24];

    int z = blockIdx.z;
    const float* A = (z == 0) ? A0 : (z == 1) ? A1 : A2;
    const float* W = (z == 0) ? W0 : (z == 1) ? W1 : W2;
    float*       C = (z == 0) ? C0 : (z == 1) ? C1 : C2;

    int bm = blockIdx.y * 128;
    int bn = blockIdx.x * 64;
    int tid = threadIdx.x;
    int wid = tid >> 5, lane = tid & 31;
    int wm = wid >> 1;
    int wn = wid & 1;
    int g  = lane >> 2;
    int t  = lane & 3;

    int ar0 = tid >> 2, ar1 = ar0 + 64, ac = (tid & 3) << 2;

    const float* Ap0 = A + (size_t)(bm + ar0) * K + ac;
    const float* Ap1 = A + (size_t)(bm + ar1) * K + ac;
    const float* Wp  = W + (size_t)(bn + ar0) * K + ac;

    float acc[2][4][4];
    #pragma unroll
    for (int mt = 0; mt < 2; mt++)
        #pragma unroll
        for (int nt = 0; nt < 4; nt++)
            #pragma unroll
            for (int r = 0; r < 4; r++) acc[mt][nt][r] = 0.0f;

    float4 ra0, ra1, rb;

    auto commitA = [&](int buf, int row, float4 v) {
        __nv_bfloat16 hx = __float2bfloat16_rn(v.x);
        __nv_bfloat16 hy = __float2bfloat16_rn(v.y);
        __nv_bfloat16 hz = __float2bfloat16_rn(v.z);
        __nv_bfloat16 hw = __float2bfloat16_rn(v.w);
        __nv_bfloat162 h01; h01.x = hx; h01.y = hy;
        __nv_bfloat162 h23; h23.x = hz; h23.y = hw;
        *(__nv_bfloat162*)&As[buf][0][row][ac]     = h01;
        *(__nv_bfloat162*)&As[buf][0][row][ac + 2] = h23;
        __nv_bfloat162 l01, l23;
        l01.x = __float2bfloat16_rn(v.x - __bfloat162float(hx));
        l01.y = __float2bfloat16_rn(v.y - __bfloat162float(hy));
        l23.x = __float2bfloat16_rn(v.z - __bfloat162float(hz));
        l23.y = __float2bfloat16_rn(v.w - __bfloat162float(hw));
        *(__nv_bfloat162*)&As[buf][1][row][ac]     = l01;
        *(__nv_bfloat162*)&As[buf][1][row][ac + 2] = l23;
    };
    auto commitB = [&](int buf, int row, float4 v) {
        __nv_bfloat16 hx = __float2bfloat16_rn(v.x);
        __nv_bfloat16 hy = __float2bfloat16_rn(v.y);
        __nv_bfloat16 hz = __float2bfloat16_rn(v.z);
        __nv_bfloat16 hw = __float2bfloat16_rn(v.w);
        __nv_bfloat162 h01; h01.x = hx; h01.y = hy;
        __nv_bfloat162 h23; h23.x = hz; h23.y = hw;
        *(__nv_bfloat162*)&Bs[buf][0][row][ac]     = h01;
        *(__nv_bfloat162*)&Bs[buf][0][row][ac + 2] = h23;
        __nv_bfloat162 l01, l23;
        l01.x = __float2bfloat16_rn(v.x - __bfloat162float(hx));
        l01.y = __float2bfloat16_rn(v.y - __bfloat162float(hy));
        l23.x = __float2bfloat16_rn(v.z - __bfloat162float(hz));
        l23.y = __float2bfloat16_rn(v.w - __bfloat162float(hw));
        *(__nv_bfloat162*)&Bs[buf][1][row][ac]     = l01;
        *(__nv_bfloat162*)&Bs[buf][1][row][ac + 2] = l23;
    };

    ra0 = *(const float4*)(Ap0);
    ra1 = *(const float4*)(Ap1);
    rb  = *(const float4*)(Wp);
    commitA(0, ar0, ra0);
    commitA(0, ar1, ra1);
    commitB(0, ar0, rb);
    ra0 = *(const float4*)(Ap0 + 16);
    ra1 = *(const float4*)(Ap1 + 16);
    rb  = *(const float4*)(Wp  + 16);
    __syncthreads();

    const int NCH = K / 16;   // 32
    for (int c = 0; c < NCH; c++) {
        int cur = c & 1, nxt = cur ^ 1;
        if (c + 1 < NCH) {
            commitA(nxt, ar0, ra0);
            commitA(nxt, ar1, ra1);
            commitB(nxt, ar0, rb);
            int k0 = (c + 2 < NCH) ? (c + 2) * 16 : (NCH - 1) * 16;
            ra0 = *(const float4*)(Ap0 + k0);
            ra1 = *(const float4*)(Ap1 + k0);
            rb  = *(const float4*)(Wp  + k0);
        }

        uint32_t ah[2][4], al[2][4], bh[4][2], bl[4][2];
        #pragma unroll
        for (int mt = 0; mt < 2; mt++) {
            int r0 = wm * 32 + mt * 16 + g;
            int r1 = r0 + 8;
            ah[mt][0] = *(const uint32_t*)&As[cur][0][r0][2 * t];
            ah[mt][1] = *(const uint32_t*)&As[cur][0][r1][2 * t];
            ah[mt][2] = *(const uint32_t*)&As[cur][0][r0][8 + 2 * t];
            ah[mt][3] = *(const uint32_t*)&As[cur][0][r1][8 + 2 * t];
            al[mt][0] = *(const uint32_t*)&As[cur][1][r0][2 * t];
            al[mt][1] = *(const uint32_t*)&As[cur][1][r1][2 * t];
            al[mt][2] = *(const uint32_t*)&As[cur][1][r0][8 + 2 * t];
            al[mt][3] = *(const uint32_t*)&As[cur][1][r1][8 + 2 * t];
        }
        #pragma unroll
        for (int nt = 0; nt < 4; nt++) {
            int n = wn * 32 + nt * 8 + g;
            bh[nt][0] = *(const uint32_t*)&Bs[cur][0][n][2 * t];
            bh[nt][1] = *(const uint32_t*)&Bs[cur][0][n][8 + 2 * t];
            bl[nt][0] = *(const uint32_t*)&Bs[cur][1][n][2 * t];
            bl[nt][1] = *(const uint32_t*)&Bs[cur][1][n][8 + 2 * t];
        }

        #pragma unroll
        for (int mt = 0; mt < 2; mt++)
            #pragma unroll
            for (int nt = 0; nt < 4; nt++) {
                MMA_BF16(acc[mt][nt], ah[mt], bh[nt]);
                MMA_BF16(acc[mt][nt], ah[mt], bl[nt]);
                MMA_BF16(acc[mt][nt], al[mt], bh[nt]);
            }
        __syncthreads();
    }

    #pragma unroll
    for (int mt = 0; mt < 2; mt++) {
        int r0 = bm + wm * 32 + mt * 16 + g;
        int r1 = r0 + 8;
        #pragma unroll
        for (int nt = 0; nt < 4; nt++) {
            int c0 = bn + wn * 32 + nt * 8 + 2 * t;
            float* d = acc[mt][nt];
            float2 bb = make_float2(0.f, 0.f);
            if (bias) bb = *(const float2*)(bias + c0);
            float2 v0 = make_float2(d[0] + bb.x, d[1] + bb.y);
            float2 v1 = make_float2(d[2] + bb.x, d[3] + bb.y);
            if (resid) {
                float2 q0 = *(const float2*)(resid + (size_t)r0 * DMODEL + c0);
                float2 q1 = *(const float2*)(resid + (size_t)r1 * DMODEL + c0);
                v0.x += q0.x; v0.y += q0.y;
                v1.x += q1.x; v1.y += q1.y;
            }
            *(float2*)(C + (size_t)r0 * DMODEL + c0) = v0;
            *(float2*)(C + (size_t)r1 * DMODEL + c0) = v1;
        }
    }
}

// ---------------------------------------------------------------------------
// Attention v2.
// Grid: 512 blocks = (bd, half). 256 threads, 8 warps; warp handles 32 q-rows
// (stride 8) within its 256-row half. K/V transposed in smem [8][512] ->
// LDS.128 conflict-free. Lane owns k = 4*lane + 128*i (i=0..3): float4 sim
// loads / attn stores. Next row's sim staged in registers (latency hiding).
// Folded 8-channel O reduction: 9 shuffles instead of 40.
// ---------------------------------------------------------------------------
__global__ __launch_bounds__(256, 3) void attn_kernel(
    const float* __restrict__ Qp, const float* __restrict__ Kp,
    const float* __restrict__ Vp, const float* __restrict__ sim,
    float* __restrict__ attn, float* __restrict__ O)
{
    __shared__ float Ks[8][512];
    __shared__ float Vs[8][512];

    int blk = blockIdx.x;       // 0..511
    int bd  = blk >> 1;
    int half = blk & 1;
    int b = bd >> 6;
    int d = bd & 63;
    int tid = threadIdx.x;

    size_t rowbase = ((size_t)b * SEQ) * DMODEL + (size_t)d * HDIM;

    // Fill K/V transposed: thread t loads rows t and t+256.
    #pragma unroll
    for (int rr = 0; rr < 2; rr++) {
        int t = tid + rr * 256;
        const float* kp = Kp + rowbase + (size_t)t * DMODEL;
        float4 x0 = *(const float4*)kp;
        float4 x1 = *(const float4*)(kp + 4);
        Ks[0][t] = x0.x; Ks[1][t] = x0.y; Ks[2][t] = x0.z; Ks[3][t] = x0.w;
        Ks[4][t] = x1.x; Ks[5][t] = x1.y; Ks[6][t] = x1.z; Ks[7][t] = x1.w;
        const float* vp = Vp + rowbase + (size_t)t * DMODEL;
        float4 y0 = *(const float4*)vp;
        float4 y1 = *(const float4*)(vp + 4);
        Vs[0][t] = y0.x; Vs[1][t] = y0.y; Vs[2][t] = y0.z; Vs[3][t] = y0.w;
        Vs[4][t] = y1.x; Vs[5][t] = y1.y; Vs[6][t] = y1.z; Vs[7][t] = y1.w;
    }
    __syncthreads();

    int warp = tid >> 5, lane = tid & 31;
    size_t simbase = (size_t)bd * (SEQ * SEQ);
    int kb = 4 * lane;          // lane's base k
    const float inv_temp = 0.125f;

    int r = half * 256 + warp;

    // stage sim for first row
    const float* sp = sim + simbase + (size_t)r * SEQ + kb;
    float4 sg0 = *(const float4*)(sp);
    float4 sg1 = *(const float4*)(sp + 128);
    float4 sg2 = *(const float4*)(sp + 256);
    float4 sg3 = *(const float4*)(sp + 384);

    for (int j = 0; j < 32; j++, r += 8) {
        float4 s0 = sg0, s1 = sg1, s2 = sg2, s3 = sg3;
        if (j < 31) {
            const float* sn = sim + simbase + (size_t)(r + 8) * SEQ + kb;
            sg0 = *(const float4*)(sn);
            sg1 = *(const float4*)(sn + 128);
            sg2 = *(const float4*)(sn + 256);
            sg3 = *(const float4*)(sn + 384);
        }

        // Q row
        const float* qrow = Qp + rowbase + (size_t)r * DMODEL;
        float4 q0 = *(const float4*)qrow;
        float4 q1 = *(const float4*)(qrow + 4);
        float qv[8] = {q0.x, q0.y, q0.z, q0.w, q1.x, q1.y, q1.z, q1.w};

        // scores: s_i = dot8(Q, K[k..k+3]) * 0.125 + sim
        float4 sa[4] = {s0, s1, s2, s3};
        #pragma unroll
        for (int i = 0; i < 4; i++) {
            int kk = kb + 128 * i;
            float4 a = make_float4(0.f, 0.f, 0.f, 0.f);
            #pragma unroll
            for (int e = 0; e < 8; e++) {
                float4 kv = *(const float4*)&Ks[e][kk];
                a.x = fmaf(qv[e], kv.x, a.x);
                a.y = fmaf(qv[e], kv.y, a.y);
                a.z = fmaf(qv[e], kv.z, a.z);
                a.w = fmaf(qv[e], kv.w, a.w);
            }
            sa[i].x = fmaf(a.x, inv_temp, sa[i].x);
            sa[i].y = fmaf(a.y, inv_temp, sa[i].y);
            sa[i].z = fmaf(a.z, inv_temp, sa[i].z);
            sa[i].w = fmaf(a.w, inv_temp, sa[i].w);
        }

        // max over 16 in-lane + warp
        float4 m01 = make_float4(fmaxf(sa[0].x, sa[1].x), fmaxf(sa[0].y, sa[1].y),
                                 fmaxf(sa[0].z, sa[1].z), fmaxf(sa[0].w, sa[1].w));
        float4 m23 = make_float4(fmaxf(sa[2].x, sa[3].x), fmaxf(sa[2].y, sa[3].y),
                                 fmaxf(sa[2].z, sa[3].z), fmaxf(sa[2].w, sa[3].w));
        float mx = fmaxf(fmaxf(fmaxf(m01.x, m23.x), fmaxf(m01.y, m23.y)),
                         fmaxf(fmaxf(m01.z, m23.z), fmaxf(m01.w, m23.w)));
        #pragma unroll
        for (int o = 16; o; o >>= 1) mx = fmaxf(mx, __shfl_xor_sync(0xffffffffu, mx, o));

        // exp, sum, and P·V accumulate
        float sum = 0.0f;
        float acc8[8] = {0.f, 0.f, 0.f, 0.f, 0.f, 0.f, 0.f, 0.f};
        #pragma unroll
        for (int i = 0; i < 4; i++) {
            float4 p;
            p.x = __expf(sa[i].x - mx);
            p.y = __expf(sa[i].y - mx);
            p.z = __expf(sa[i].z - mx);
            p.w = __expf(sa[i].w - mx);
            sa[i] = p;
            sum += (p.x + p.y) + (p.z + p.w);
            int kk = kb + 128 * i;
            #pragma unroll
            for (int e = 0; e < 8; e++) {
                float4 vv = *(const float4*)&Vs[e][kk];
                acc8[e] = fmaf(p.x, vv.x, acc8[e]);
                acc8[e] = fmaf(p.y, vv.y, acc8[e]);
                acc8[e] = fmaf(p.z, vv.z, acc8[e]);
                acc8[e] = fmaf(p.w, vv.w, acc8[e]);
            }
        }
        #pragma unroll
        for (int o = 16; o; o >>= 1) sum += __shfl_xor_sync(0xffffffffu, sum, o);
        float inv = 1.0f / sum;

        // attn output (normalized P)
        if (attn) {
            float* arow = attn + simbase + (size_t)r * SEQ + kb;
            #pragma unroll
            for (int i = 0; i < 4; i++) {
                float4 w = make_float4(sa[i].x * inv, sa[i].y * inv,
                                       sa[i].z * inv, sa[i].w * inv);
                *(float4*)(arow + 128 * i) = w;
            }
        }

        // folded channel reduction: 8 channels over 32 lanes, 9 shuffles
        bool hi16 = (lane & 16) != 0;
        float red4[4];
        #pragma unroll
        for (int c = 0; c < 4; c++) {
            float send = hi16 ? acc8[c] : acc8[c + 4];
            float recv = __shfl_xor_sync(0xffffffffu, send, 16);
            red4[c] = (hi16 ? acc8[c + 4] : acc8[c]) + recv;
        }
        bool hi8 = (lane & 8) != 0;
        float red2v[2];
        #pragma unroll
        for (int c = 0; c < 2; c++) {
            float send = hi8 ? red4[c] : red4[c + 2];
            float recv = __shfl_xor_sync(0xffffffffu, send, 8);
            red2v[c] = (hi8 ? red4[c + 2] : red4[c]) + recv;
        }
        bool hi4 = (lane & 4) != 0;
        {
            float send = hi4 ? red2v[0] : red2v[1];
            float recv = __shfl_xor_sync(0xffffffffu, send, 4);
            float rv = (hi4 ? red2v[1] : red2v[0]) + recv;
            rv += __shfl_xor_sync(0xffffffffu, rv, 2);
            rv += __shfl_xor_sync(0xffffffffu, rv, 1);
            // lane holds channel ch = bit4*4 + bit3*2 + bit2*1
            if ((lane & 3) == 0) {
                int ch = (lane >> 2) & 7;
                O[rowbase + (size_t)r * DMODEL + ch] = rv * inv;
            }
        }
    }
}

// ---------------------------------------------------------------------------
// Launch: ln, qkv(batched, tensor), attn, fc(tensor) — 4 launches.
// ---------------------------------------------------------------------------
extern "C" void kernel_launch(void* const* d_in, const int* in_sizes, int n_in,
                              void* d_out, int out_size)
{
    const float* q   = (const float*)d_in[0];
    const float* k   = (const float*)d_in[1];
    const float* v   = (const float*)d_in[2];
    const float* sim = (const float*)d_in[3];
    const float* Wq  = (const float*)d_in[4];
    const float* Wk  = (const float*)d_in[5];
    const float* Wv  = (const float*)d_in[6];
    const float* Wfc = (const float*)d_in[7];
    const float* bfc = (const float*)d_in[8];
    const float* lng = (const float*)d_in[9];
    const float* lnb = (const float*)d_in[10];

    float *qn, *Qp, *Kp, *Vp, *O;
    cudaGetSymbolAddress((void**)&qn, g_qn);
    cudaGetSymbolAddress((void**)&Qp, g_Qp);
    cudaGetSymbolAddress((void**)&Kp, g_Kp);
    cudaGetSymbolAddress((void**)&Vp, g_Vp);
    cudaGetSymbolAddress((void**)&O,  g_O);

    float* outp = (float*)d_out;
    float* attnp = nullptr;
    const long long NOUT  = (long long)MROWS * DMODEL;
    const long long NATTN = (long long)BATCH * NHEADS * SEQ * SEQ;
    if ((long long)out_size >= NOUT + NATTN) attnp = outp + NOUT;

    // 1) LayerNorm(q)
    ln_kernel<<<MROWS, 256>>>(q, lng, lnb, qn);

    // 2) Batched QKV projections (tensor cores, 384 CTAs)
    dim3 gqkv(DMODEL / 64, MROWS / 128, 3);
    gemm_bf16x3<<<gqkv, 256>>>(qn, k, v, Wq, Wk, Wv, Qp, Kp, Vp,
                               nullptr, nullptr);

    // 3) Attention v2 (512 blocks x 256 threads)
    attn_kernel<<<2 * BATCH * NHEADS, 256>>>(Qp, Kp, Vp, sim, attnp, O);

    // 4) FC + bias + residual (tensor cores)
    dim3 gfc(DMODEL / 64, MROWS / 128, 1);
    gemm_bf16x3<<<gfc, 256>>>(O, O, O, Wfc, Wfc, Wfc, outp, outp, outp,
                              bfc, q);
}

// round 8
// speedup vs baseline: 1.2854x; 1.2854x over previous
#include <cuda_runtime.h>
#include <cuda_bf16.h>
#include <cstdint>

#define BATCH   4
#define SEQ     512
#define DMODEL  512
#define MROWS   (BATCH * SEQ)       // 2048
#define NHEADS  64                  // "head" axis = d_k in this module
#define HDIM    8                   // per-head feature dim

// ---------------------------------------------------------------------------
// Scratch (no cudaMalloc allowed)
// ---------------------------------------------------------------------------
__device__ float g_qn[MROWS * DMODEL];
__device__ float g_Qp[MROWS * DMODEL];
__device__ float g_Kp[MROWS * DMODEL];
__device__ float g_Vp[MROWS * DMODEL];
__device__ float g_O [MROWS * DMODEL];

// ---------------------------------------------------------------------------
// LayerNorm over last dim (512), one block per row
// ---------------------------------------------------------------------------
__global__ __launch_bounds__(256) void ln_kernel(
    const float* __restrict__ x, const float* __restrict__ gamma,
    const float* __restrict__ beta, float* __restrict__ out)
{
    int row = blockIdx.x;
    const float* xr = x + (size_t)row * DMODEL;
    int tid = threadIdx.x;
    float a0 = xr[tid];
    float a1 = xr[tid + 256];

    __shared__ float red[8];
    __shared__ float red2[8];
    int warp = tid >> 5, lane = tid & 31;

    float s = a0 + a1;
    #pragma unroll
    for (int o = 16; o; o >>= 1) s += __shfl_xor_sync(0xffffffffu, s, o);
    if (lane == 0) red[warp] = s;
    __syncthreads();
    float mean = (red[0] + red[1] + red[2] + red[3] +
                  red[4] + red[5] + red[6] + red[7]) * (1.0f / 512.0f);

    float d0 = a0 - mean, d1 = a1 - mean;
    float vs = d0 * d0 + d1 * d1;
    #pragma unroll
    for (int o = 16; o; o >>= 1) vs += __shfl_xor_sync(0xffffffffu, vs, o);
    if (lane == 0) red2[warp] = vs;
    __syncthreads();
    float var = (red2[0] + red2[1] + red2[2] + red2[3] +
                 red2[4] + red2[5] + red2[6] + red2[7]) * (1.0f / 512.0f);
    float inv = rsqrtf(var + 1e-6f);

    float* orow = out + (size_t)row * DMODEL;
    orow[tid]       = d0 * inv * gamma[tid]       + beta[tid];
    orow[tid + 256] = d1 * inv * gamma[tid + 256] + beta[tid + 256];
}

// ---------------------------------------------------------------------------
// Tensor-core GEMM (bf16 3-pass split, fp32 accumulate) — unchanged winner.
// ---------------------------------------------------------------------------
#define MMA_BF16(d, a, b)                                                    \
    asm volatile(                                                            \
        "mma.sync.aligned.m16n8k16.row.col.f32.bf16.bf16.f32 "              \
        "{%0,%1,%2,%3}, {%4,%5,%6,%7}, {%8,%9}, {%0,%1,%2,%3};"             \
        : "+f"(d[0]), "+f"(d[1]), "+f"(d[2]), "+f"(d[3])                     \
        : "r"(a[0]), "r"(a[1]), "r"(a[2]), "r"(a[3]), "r"(b[0]), "r"(b[1]))

__global__ __launch_bounds__(256) void gemm_bf16x3(
    const float* __restrict__ A0, const float* __restrict__ A1,
    const float* __restrict__ A2,
    const float* __restrict__ W0, const float* __restrict__ W1,
    const float* __restrict__ W2,
    float* __restrict__ C0, float* __restrict__ C1, float* __restrict__ C2,
    const float* __restrict__ bias, const float* __restrict__ resid)
{
    const int K = DMODEL;
    __shared__ __nv_bfloat16 As[2][2][128][24];
    __shared__ __nv_bfloat16 Bs[2][2][64][24];

    int z = blockIdx.z;
    const float* A = (z == 0) ? A0 : (z == 1) ? A1 : A2;
    const float* W = (z == 0) ? W0 : (z == 1) ? W1 : W2;
    float*       C = (z == 0) ? C0 : (z == 1) ? C1 : C2;

    int bm = blockIdx.y * 128;
    int bn = blockIdx.x * 64;
    int tid = threadIdx.x;
    int wid = tid >> 5, lane = tid & 31;
    int wm = wid >> 1;
    int wn = wid & 1;
    int g  = lane >> 2;
    int t  = lane & 3;

    int ar0 = tid >> 2, ar1 = ar0 + 64, ac = (tid & 3) << 2;

    const float* Ap0 = A + (size_t)(bm + ar0) * K + ac;
    const float* Ap1 = A + (size_t)(bm + ar1) * K + ac;
    const float* Wp  = W + (size_t)(bn + ar0) * K + ac;

    float acc[2][4][4];
    #pragma unroll
    for (int mt = 0; mt < 2; mt++)
        #pragma unroll
        for (int nt = 0; nt < 4; nt++)
            #pragma unroll
            for (int r = 0; r < 4; r++) acc[mt][nt][r] = 0.0f;

    float4 ra0, ra1, rb;

    auto commitA = [&](int buf, int row, float4 v) {
        __nv_bfloat16 hx = __float2bfloat16_rn(v.x);
        __nv_bfloat16 hy = __float2bfloat16_rn(v.y);
        __nv_bfloat16 hz = __float2bfloat16_rn(v.z);
        __nv_bfloat16 hw = __float2bfloat16_rn(v.w);
        __nv_bfloat162 h01; h01.x = hx; h01.y = hy;
        __nv_bfloat162 h23; h23.x = hz; h23.y = hw;
        *(__nv_bfloat162*)&As[buf][0][row][ac]     = h01;
        *(__nv_bfloat162*)&As[buf][0][row][ac + 2] = h23;
        __nv_bfloat162 l01, l23;
        l01.x = __float2bfloat16_rn(v.x - __bfloat162float(hx));
        l01.y = __float2bfloat16_rn(v.y - __bfloat162float(hy));
        l23.x = __float2bfloat16_rn(v.z - __bfloat162float(hz));
        l23.y = __float2bfloat16_rn(v.w - __bfloat162float(hw));
        *(__nv_bfloat162*)&As[buf][1][row][ac]     = l01;
        *(__nv_bfloat162*)&As[buf][1][row][ac + 2] = l23;
    };
    auto commitB = [&](int buf, int row, float4 v) {
        __nv_bfloat16 hx = __float2bfloat16_rn(v.x);
        __nv_bfloat16 hy = __float2bfloat16_rn(v.y);
        __nv_bfloat16 hz = __float2bfloat16_rn(v.z);
        __nv_bfloat16 hw = __float2bfloat16_rn(v.w);
        __nv_bfloat162 h01; h01.x = hx; h01.y = hy;
        __nv_bfloat162 h23; h23.x = hz; h23.y = hw;
        *(__nv_bfloat162*)&Bs[buf][0][row][ac]     = h01;
        *(__nv_bfloat162*)&Bs[buf][0][row][ac + 2] = h23;
        __nv_bfloat162 l01, l23;
        l01.x = __float2bfloat16_rn(v.x - __bfloat162float(hx));
        l01.y = __float2bfloat16_rn(v.y - __bfloat162float(hy));
        l23.x = __float2bfloat16_rn(v.z - __bfloat162float(hz));
        l23.y = __float2bfloat16_rn(v.w - __bfloat162float(hw));
        *(__nv_bfloat162*)&Bs[buf][1][row][ac]     = l01;
        *(__nv_bfloat162*)&Bs[buf][1][row][ac + 2] = l23;
    };

    ra0 = *(const float4*)(Ap0);
    ra1 = *(const float4*)(Ap1);
    rb  = *(const float4*)(Wp);
    commitA(0, ar0, ra0);
    commitA(0, ar1, ra1);
    commitB(0, ar0, rb);
    ra0 = *(const float4*)(Ap0 + 16);
    ra1 = *(const float4*)(Ap1 + 16);
    rb  = *(const float4*)(Wp  + 16);
    __syncthreads();

    const int NCH = K / 16;   // 32
    for (int c = 0; c < NCH; c++) {
        int cur = c & 1, nxt = cur ^ 1;
        if (c + 1 < NCH) {
            commitA(nxt, ar0, ra0);
            commitA(nxt, ar1, ra1);
            commitB(nxt, ar0, rb);
            int k0 = (c + 2 < NCH) ? (c + 2) * 16 : (NCH - 1) * 16;
            ra0 = *(const float4*)(Ap0 + k0);
            ra1 = *(const float4*)(Ap1 + k0);
            rb  = *(const float4*)(Wp  + k0);
        }

        uint32_t ah[2][4], al[2][4], bh[4][2], bl[4][2];
        #pragma unroll
        for (int mt = 0; mt < 2; mt++) {
            int r0 = wm * 32 + mt * 16 + g;
            int r1 = r0 + 8;
            ah[mt][0] = *(const uint32_t*)&As[cur][0][r0][2 * t];
            ah[mt][1] = *(const uint32_t*)&As[cur][0][r1][2 * t];
            ah[mt][2] = *(const uint32_t*)&As[cur][0][r0][8 + 2 * t];
            ah[mt][3] = *(const uint32_t*)&As[cur][0][r1][8 + 2 * t];
            al[mt][0] = *(const uint32_t*)&As[cur][1][r0][2 * t];
            al[mt][1] = *(const uint32_t*)&As[cur][1][r1][2 * t];
            al[mt][2] = *(const uint32_t*)&As[cur][1][r0][8 + 2 * t];
            al[mt][3] = *(const uint32_t*)&As[cur][1][r1][8 + 2 * t];
        }
        #pragma unroll
        for (int nt = 0; nt < 4; nt++) {
            int n = wn * 32 + nt * 8 + g;
            bh[nt][0] = *(const uint32_t*)&Bs[cur][0][n][2 * t];
            bh[nt][1] = *(const uint32_t*)&Bs[cur][0][n][8 + 2 * t];
            bl[nt][0] = *(const uint32_t*)&Bs[cur][1][n][2 * t];
            bl[nt][1] = *(const uint32_t*)&Bs[cur][1][n][8 + 2 * t];
        }

        #pragma unroll
        for (int mt = 0; mt < 2; mt++)
            #pragma unroll
            for (int nt = 0; nt < 4; nt++) {
                MMA_BF16(acc[mt][nt], ah[mt], bh[nt]);
                MMA_BF16(acc[mt][nt], ah[mt], bl[nt]);
                MMA_BF16(acc[mt][nt], al[mt], bh[nt]);
            }
        __syncthreads();
    }

    #pragma unroll
    for (int mt = 0; mt < 2; mt++) {
        int r0 = bm + wm * 32 + mt * 16 + g;
        int r1 = r0 + 8;
        #pragma unroll
        for (int nt = 0; nt < 4; nt++) {
            int c0 = bn + wn * 32 + nt * 8 + 2 * t;
            float* d = acc[mt][nt];
            float2 bb = make_float2(0.f, 0.f);
            if (bias) bb = *(const float2*)(bias + c0);
            float2 v0 = make_float2(d[0] + bb.x, d[1] + bb.y);
            float2 v1 = make_float2(d[2] + bb.x, d[3] + bb.y);
            if (resid) {
                float2 q0 = *(const float2*)(resid + (size_t)r0 * DMODEL + c0);
                float2 q1 = *(const float2*)(resid + (size_t)r1 * DMODEL + c0);
                v0.x += q0.x; v0.y += q0.y;
                v1.x += q1.x; v1.y += q1.y;
            }
            *(float2*)(C + (size_t)r0 * DMODEL + c0) = v0;
            *(float2*)(C + (size_t)r1 * DMODEL + c0) = v1;
        }
    }
}

// ---------------------------------------------------------------------------
// Attention v3: K/V held in REGISTERS for the whole block.
// Grid: 256 blocks (one per bd), 256 threads = 8 warps = 2 row-groups x 4
// k-warps. Lane owns 4 k's (k = wk*128 + 4*lane): K/V = 32+32 regs, loaded
// once. Per row: float4 sim load (prefetched), 64 FMA, two __syncthreads
// for cross-warp max/sum reductions. Near-zero smem traffic.
// ---------------------------------------------------------------------------
__global__ __launch_bounds__(256, 2) void attn_kernel(
    const float* __restrict__ Qp, const float* __restrict__ Kp,
    const float* __restrict__ Vp, const float* __restrict__ sim,
    float* __restrict__ attn, float* __restrict__ O)
{
    __shared__ float redmax[2][4];
    __shared__ float redsum[2][4];
    __shared__ float redpv[2][4][8];

    int bd = blockIdx.x;
    int b = bd >> 6, d = bd & 63;
    int tid = threadIdx.x;
    int warp = tid >> 5, lane = tid & 31;
    int g  = warp >> 2;      // row group 0/1
    int wk = warp & 3;       // k quarter
    int k0 = wk * 128 + lane * 4;

    size_t rowbase = ((size_t)b * SEQ) * DMODEL + (size_t)d * HDIM;
    size_t simbase = (size_t)bd * (SEQ * SEQ);

    // K/V for this lane's 4 k's -> registers (once per block)
    float Kr[4][8], Vr[4][8];
    #pragma unroll
    for (int jj = 0; jj < 4; jj++) {
        const float* kp = Kp + rowbase + (size_t)(k0 + jj) * DMODEL;
        float4 a0 = *(const float4*)kp;
        float4 a1 = *(const float4*)(kp + 4);
        Kr[jj][0] = a0.x; Kr[jj][1] = a0.y; Kr[jj][2] = a0.z; Kr[jj][3] = a0.w;
        Kr[jj][4] = a1.x; Kr[jj][5] = a1.y; Kr[jj][6] = a1.z; Kr[jj][7] = a1.w;
        const float* vp = Vp + rowbase + (size_t)(k0 + jj) * DMODEL;
        float4 b0 = *(const float4*)vp;
        float4 b1 = *(const float4*)(vp + 4);
        Vr[jj][0] = b0.x; Vr[jj][1] = b0.y; Vr[jj][2] = b0.z; Vr[jj][3] = b0.w;
        Vr[jj][4] = b1.x; Vr[jj][5] = b1.y; Vr[jj][6] = b1.z; Vr[jj][7] = b1.w;
    }

    const float inv_temp = 0.125f;
    int r = g;   // group g handles rows r = g, g+2, ..., 256 rows

    // prefetch first row's sim + Q
    float4 sg4 = *(const float4*)(sim + simbase + (size_t)r * SEQ + k0);
    const float* qp0 = Qp + rowbase + (size_t)r * DMODEL;
    float4 qg0 = *(const float4*)qp0;
    float4 qg1 = *(const float4*)(qp0 + 4);

    for (int j = 0; j < 256; j++, r += 2) {
        float4 sv = sg4;
        float qv[8] = {qg0.x, qg0.y, qg0.z, qg0.w, qg1.x, qg1.y, qg1.z, qg1.w};
        if (j < 255) {
            const float* sn = sim + simbase + (size_t)(r + 2) * SEQ + k0;
            sg4 = *(const float4*)sn;
            const float* qn = Qp + rowbase + (size_t)(r + 2) * DMODEL;
            qg0 = *(const float4*)qn;
            qg1 = *(const float4*)(qn + 4);
        }

        // scores for lane's 4 k's
        float s0, s1, s2, s3;
        {
            float a0 = 0.f, a1 = 0.f, a2 = 0.f, a3 = 0.f;
            #pragma unroll
            for (int e = 0; e < 8; e++) {
                a0 = fmaf(qv[e], Kr[0][e], a0);
                a1 = fmaf(qv[e], Kr[1][e], a1);
                a2 = fmaf(qv[e], Kr[2][e], a2);
                a3 = fmaf(qv[e], Kr[3][e], a3);
            }
            s0 = fmaf(a0, inv_temp, sv.x);
            s1 = fmaf(a1, inv_temp, sv.y);
            s2 = fmaf(a2, inv_temp, sv.z);
            s3 = fmaf(a3, inv_temp, sv.w);
        }

        // warp max, then cross-warp via smem
        float mx = fmaxf(fmaxf(s0, s1), fmaxf(s2, s3));
        #pragma unroll
        for (int o = 16; o; o >>= 1) mx = fmaxf(mx, __shfl_xor_sync(0xffffffffu, mx, o));
        if (lane == 0) redmax[g][wk] = mx;
        __syncthreads();
        mx = fmaxf(fmaxf(redmax[g][0], redmax[g][1]),
                   fmaxf(redmax[g][2], redmax[g][3]));

        // exp, partial sum, PV accumulate
        float p0 = __expf(s0 - mx);
        float p1 = __expf(s1 - mx);
        float p2 = __expf(s2 - mx);
        float p3 = __expf(s3 - mx);
        float sum = (p0 + p1) + (p2 + p3);
        #pragma unroll
        for (int o = 16; o; o >>= 1) sum += __shfl_xor_sync(0xffffffffu, sum, o);

        float acc8[8];
        #pragma unroll
        for (int e = 0; e < 8; e++)
            acc8[e] = fmaf(p0, Vr[0][e],
                      fmaf(p1, Vr[1][e],
                      fmaf(p2, Vr[2][e], p3 * Vr[3][e])));

        // folded 8-channel warp reduction (validated in round 7)
        bool hi16 = (lane & 16) != 0;
        float red4[4];
        #pragma unroll
        for (int c = 0; c < 4; c++) {
            float send = hi16 ? acc8[c] : acc8[c + 4];
            float recv = __shfl_xor_sync(0xffffffffu, send, 16);
            red4[c] = (hi16 ? acc8[c + 4] : acc8[c]) + recv;
        }
        bool hi8 = (lane & 8) != 0;
        float red2v[2];
        #pragma unroll
        for (int c = 0; c < 2; c++) {
            float send = hi8 ? red4[c] : red4[c + 2];
            float recv = __shfl_xor_sync(0xffffffffu, send, 8);
            red2v[c] = (hi8 ? red4[c + 2] : red4[c]) + recv;
        }
        bool hi4 = (lane & 4) != 0;
        float rv;
        {
            float send = hi4 ? red2v[0] : red2v[1];
            float recv = __shfl_xor_sync(0xffffffffu, send, 4);
            rv = (hi4 ? red2v[1] : red2v[0]) + recv;
            rv += __shfl_xor_sync(0xffffffffu, rv, 2);
            rv += __shfl_xor_sync(0xffffffffu, rv, 1);
        }
        if (lane == 0) redsum[g][wk] = sum;
        if ((lane & 3) == 0) redpv[g][wk][(lane >> 2) & 7] = rv;
        __syncthreads();

        float tsum = (redsum[g][0] + redsum[g][1]) +
                     (redsum[g][2] + redsum[g][3]);
        float inv = 1.0f / tsum;

        if (attn) {
            float* arow = attn + simbase + (size_t)r * SEQ + k0;
            float4 w = make_float4(p0 * inv, p1 * inv, p2 * inv, p3 * inv);
            *(float4*)arow = w;
        }
        if (wk == 0 && (lane & 3) == 0) {
            int ch = (lane >> 2) & 7;
            float ov = ((redpv[g][0][ch] + redpv[g][1][ch]) +
                        (redpv[g][2][ch] + redpv[g][3][ch])) * inv;
            O[rowbase + (size_t)r * DMODEL + ch] = ov;
        }
    }
}

// ---------------------------------------------------------------------------
// Launch: ln, qkv(batched, tensor), attn, fc(tensor) — 4 launches.
// ---------------------------------------------------------------------------
extern "C" void kernel_launch(void* const* d_in, const int* in_sizes, int n_in,
                              void* d_out, int out_size)
{
    const float* q   = (const float*)d_in[0];
    const float* k   = (const float*)d_in[1];
    const float* v   = (const float*)d_in[2];
    const float* sim = (const float*)d_in[3];
    const float* Wq  = (const float*)d_in[4];
    const float* Wk  = (const float*)d_in[5];
    const float* Wv  = (const float*)d_in[6];
    const float* Wfc = (const float*)d_in[7];
    const float* bfc = (const float*)d_in[8];
    const float* lng = (const float*)d_in[9];
    const float* lnb = (const float*)d_in[10];

    float *qn, *Qp, *Kp, *Vp, *O;
    cudaGetSymbolAddress((void**)&qn, g_qn);
    cudaGetSymbolAddress((void**)&Qp, g_Qp);
    cudaGetSymbolAddress((void**)&Kp, g_Kp);
    cudaGetSymbolAddress((void**)&Vp, g_Vp);
    cudaGetSymbolAddress((void**)&O,  g_O);

    float* outp = (float*)d_out;
    float* attnp = nullptr;
    const long long NOUT  = (long long)MROWS * DMODEL;
    const long long NATTN = (long long)BATCH * NHEADS * SEQ * SEQ;
    if ((long long)out_size >= NOUT + NATTN) attnp = outp + NOUT;

    // 1) LayerNorm(q)
    ln_kernel<<<MROWS, 256>>>(q, lng, lnb, qn);

    // 2) Batched QKV projections (tensor cores, 384 CTAs)
    dim3 gqkv(DMODEL / 64, MROWS / 128, 3);
    gemm_bf16x3<<<gqkv, 256>>>(qn, k, v, Wq, Wk, Wv, Qp, Kp, Vp,
                               nullptr, nullptr);

    // 3) Attention v3 (256 blocks x 256 threads, K/V in registers)
    attn_kernel<<<BATCH * NHEADS, 256>>>(Qp, Kp, Vp, sim, attnp, O);

    // 4) FC + bias + residual (tensor cores)
    dim3 gfc(DMODEL / 64, MROWS / 128, 1);
    gemm_bf16x3<<<gfc, 256>>>(O, O, O, Wfc, Wfc, Wfc, outp, outp, outp,
                              bfc, q);
}